// round 4
// baseline (speedup 1.0000x reference)
#include <cuda_runtime.h>
#include <cstdint>

#define EMBED 768
#define HEAD 64
#define SEQ 4096
#define BATCH 4

// Scratch for Q, K, V projections: [B*T, 64] each, tf32-rounded fp32 bits
__device__ float g_Q[BATCH * SEQ * HEAD];
__device__ float g_K[BATCH * SEQ * HEAD];
__device__ float g_V[BATCH * SEQ * HEAD];

__device__ __forceinline__ uint32_t f2tf32(float x) {
    uint32_t r;
    asm("cvt.rna.tf32.f32 %0, %1;" : "=r"(r) : "f"(x));
    return r;
}

// D = A(16x8,row) * B(8x8,col) + D, tf32 inputs, f32 accum
__device__ __forceinline__ void mma_tf32(float c[4],
    uint32_t a0, uint32_t a1, uint32_t a2, uint32_t a3,
    uint32_t b0, uint32_t b1)
{
    asm volatile(
        "mma.sync.aligned.m16n8k8.row.col.f32.tf32.tf32.f32 "
        "{%0,%1,%2,%3}, {%4,%5,%6,%7}, {%8,%9}, {%0,%1,%2,%3};"
        : "+f"(c[0]), "+f"(c[1]), "+f"(c[2]), "+f"(c[3])
        : "r"(a0), "r"(a1), "r"(a2), "r"(a3), "r"(b0), "r"(b1));
}

__device__ __forceinline__ uint32_t s2u(const void* p) {
    uint32_t a;
    asm("{ .reg .u64 t; cvta.to.shared.u64 t, %1; cvt.u32.u64 %0, t; }"
        : "=r"(a) : "l"(p));
    return a;
}

#define CPA16(dst, src) \
    asm volatile("cp.async.cg.shared.global [%0], [%1], 16;" :: "r"(dst), "l"(src) : "memory")
#define CPA_COMMIT() asm volatile("cp.async.commit_group;" ::: "memory")
#define CPA_WAIT1()  asm volatile("cp.async.wait_group 1;" ::: "memory")
#define CPA_WAIT0()  asm volatile("cp.async.wait_group 0;" ::: "memory")

// ---------------------------------------------------------------------------
// QKV projection via tf32 mma. BM=128, 256 threads (8 warps), grid (128, 3).
// Outputs stored as tf32-rounded fp32 so flash can raw-copy them.
// ---------------------------------------------------------------------------
__global__ __launch_bounds__(256, 2) void qkv_kernel(
    const float* __restrict__ x,
    const float* __restrict__ Wq, const float* __restrict__ bq,
    const float* __restrict__ Wk, const float* __restrict__ bk,
    const float* __restrict__ Wv, const float* __restrict__ bv)
{
    extern __shared__ uint32_t dsm[];
    uint32_t* sx = dsm;                 // 128 x 68
    uint32_t* sw = dsm + 128 * 68;      // 64 x 72

    const float* __restrict__ W;
    const float* __restrict__ bias;
    float* out;
    if (blockIdx.y == 0)      { W = Wq; bias = bq; out = g_Q; }
    else if (blockIdx.y == 1) { W = Wk; bias = bk; out = g_K; }
    else                      { W = Wv; bias = bv; out = g_V; }

    const int t    = threadIdx.x;
    const int lane = t & 31;
    const int w16  = (t >> 5) << 4;
    const int gid  = lane >> 2;
    const int l3   = lane & 3;
    const int row0 = blockIdx.x * 128;

    float o[8][4];
#pragma unroll
    for (int n = 0; n < 8; n++)
#pragma unroll
        for (int c = 0; c < 4; c++) o[n][c] = 0.f;

    for (int e0 = 0; e0 < EMBED; e0 += 64) {
        __syncthreads();
#pragma unroll
        for (int i = 0; i < 8; i++) {
            int fi = t + i * 256;
            int r  = fi >> 4;
            int c  = (fi & 15) << 2;
            float4 xv = *(const float4*)&x[(size_t)(row0 + r) * EMBED + e0 + c];
            sx[r * 68 + c + 0] = f2tf32(xv.x);
            sx[r * 68 + c + 1] = f2tf32(xv.y);
            sx[r * 68 + c + 2] = f2tf32(xv.z);
            sx[r * 68 + c + 3] = f2tf32(xv.w);
        }
#pragma unroll
        for (int i = 0; i < 4; i++) {
            int fi = t + i * 256;
            int r  = fi >> 4;
            int c  = (fi & 15) << 2;
            float4 wv = *(const float4*)&W[(size_t)(e0 + r) * HEAD + c];
            sw[r * 72 + c + 0] = f2tf32(wv.x);
            sw[r * 72 + c + 1] = f2tf32(wv.y);
            sw[r * 72 + c + 2] = f2tf32(wv.z);
            sw[r * 72 + c + 3] = f2tf32(wv.w);
        }
        __syncthreads();

#pragma unroll
        for (int ks = 0; ks < 8; ks++) {
            int h = 8 * ks;
            uint32_t a0 = sx[(w16 + gid) * 68 + h + l3];
            uint32_t a1 = sx[(w16 + gid + 8) * 68 + h + l3];
            uint32_t a2 = sx[(w16 + gid) * 68 + h + l3 + 4];
            uint32_t a3 = sx[(w16 + gid + 8) * 68 + h + l3 + 4];
#pragma unroll
            for (int n = 0; n < 8; n++) {
                uint32_t b0 = sw[(h + l3) * 72 + 8 * n + gid];
                uint32_t b1 = sw[(h + l3 + 4) * 72 + 8 * n + gid];
                mma_tf32(o[n], a0, a1, a2, a3, b0, b1);
            }
        }
    }

#pragma unroll
    for (int n = 0; n < 8; n++) {
        int cbase = 8 * n + 2 * l3;
        float b0 = bias[cbase], b1 = bias[cbase + 1];
        float2 r0v = make_float2(__uint_as_float(f2tf32(o[n][0] + b0)),
                                 __uint_as_float(f2tf32(o[n][1] + b1)));
        float2 r1v = make_float2(__uint_as_float(f2tf32(o[n][2] + b0)),
                                 __uint_as_float(f2tf32(o[n][3] + b1)));
        *(float2*)&out[(size_t)(row0 + w16 + gid) * HEAD + cbase]     = r0v;
        *(float2*)&out[(size_t)(row0 + w16 + gid + 8) * HEAD + cbase] = r1v;
    }
}

// ---------------------------------------------------------------------------
// Flash attention, causal, tf32 mma, split-kn across 2 warp-groups.
// BM=64, 256 threads. Group g (warps 4g..4g+3) owns k-columns 32g..32g+31 of
// EVERY kt tile, with private (m,l,O) merged once at the end. K/V tiles are
// shared by the whole block and double-buffered via cp.async.
// smem (words): sQ[0,4352) K[4352,13056) V[13056,22272) P[22272,26880)
// ---------------------------------------------------------------------------
__global__ __launch_bounds__(256, 2) void flash_kernel(float* __restrict__ out)
{
    extern __shared__ uint32_t smem[];
    const int SK = 4352, SV = 13056, SP = 22272;
    uint32_t* sQ = smem;

    const int b    = blockIdx.y;
    const int qt   = (int)gridDim.x - 1 - (int)blockIdx.x;  // heavy tiles first
    const int t    = threadIdx.x;
    const int lane = t & 31;
    const int warp = t >> 5;
    const int g    = warp >> 2;          // column-group 0/1
    const int w16  = (warp & 3) << 4;
    const int gid  = lane >> 2;
    const int l3   = lane & 3;
    const int r0   = w16 + gid;          // local q row (first of pair)

    uint32_t* sPg = smem + SP + g * 2304;     // 64 x 36, group-private P

    const float* __restrict__ Q = g_Q + (size_t)b * SEQ * HEAD;
    const float* __restrict__ K = g_K + (size_t)b * SEQ * HEAD;
    const float* __restrict__ V = g_V + (size_t)b * SEQ * HEAD;

    const uint32_t su = s2u(smem);

    // ---- prologue: async-load Q, K0/V0 (group A) and K1/V1 (group B) ----
#pragma unroll
    for (int i = 0; i < 4; i++) {
        int id = t + i * 256;
        int r  = id >> 4;
        int c  = (id & 15) << 2;
        CPA16(su + (r * 68 + c) * 4, &Q[(size_t)(qt * 64 + r) * HEAD + c]);
        CPA16(su + (SK + r * 68 + c) * 4, &K[(size_t)(0 * 64 + r) * HEAD + c]);
        CPA16(su + (SV + r * 72 + c) * 4, &V[(size_t)(0 * 64 + r) * HEAD + c]);
    }
    CPA_COMMIT();
#pragma unroll
    for (int i = 0; i < 4; i++) {
        int id = t + i * 256;
        int r  = id >> 4;
        int c  = (id & 15) << 2;
        CPA16(su + (SK + 4352 + r * 68 + c) * 4, &K[(size_t)(64 + r) * HEAD + c]);
        CPA16(su + (SV + 4608 + r * 72 + c) * 4, &V[(size_t)(64 + r) * HEAD + c]);
    }
    CPA_COMMIT();

    float m0 = -1e30f, m1 = -1e30f, l0 = 0.f, l1 = 0.f;
    float o[8][4];
#pragma unroll
    for (int n = 0; n < 8; n++)
#pragma unroll
        for (int c = 0; c < 4; c++) o[n][c] = 0.f;

    for (int kt = 0; kt <= qt; kt++) {
        CPA_WAIT1();          // tile kt (and Q) landed
        __syncthreads();

        const int st = kt & 1;
        uint32_t* sKc = smem + SK + st * 4352;
        uint32_t* sVc = smem + SV + st * 4608;

        // S_half = Q (16x64) . K_half(32x64)^T per warp
        float s[4][4];
#pragma unroll
        for (int n = 0; n < 4; n++)
#pragma unroll
            for (int c = 0; c < 4; c++) s[n][c] = 0.f;

#pragma unroll
        for (int ks = 0; ks < 8; ks++) {
            int h = 8 * ks;
            uint32_t a0 = sQ[(r0) * 68 + h + l3];
            uint32_t a1 = sQ[(r0 + 8) * 68 + h + l3];
            uint32_t a2 = sQ[(r0) * 68 + h + l3 + 4];
            uint32_t a3 = sQ[(r0 + 8) * 68 + h + l3 + 4];
#pragma unroll
            for (int n = 0; n < 4; n++) {
                int kr = 32 * g + 8 * n + gid;
                uint32_t b0 = sKc[kr * 68 + h + l3];
                uint32_t b1 = sKc[kr * 68 + h + l3 + 4];
                mma_tf32(s[n], a0, a1, a2, a3, b0, b1);
            }
        }

        // Scale + causal mask (diagonal tile only)
        const float scale = 0.125f;
        if (kt == qt) {
#pragma unroll
            for (int n = 0; n < 4; n++) {
                int c0 = 32 * g + 8 * n + 2 * l3;
                s[n][0] = (c0     <= r0    ) ? s[n][0] * scale : -1e30f;
                s[n][1] = (c0 + 1 <= r0    ) ? s[n][1] * scale : -1e30f;
                s[n][2] = (c0     <= r0 + 8) ? s[n][2] * scale : -1e30f;
                s[n][3] = (c0 + 1 <= r0 + 8) ? s[n][3] * scale : -1e30f;
            }
        } else {
#pragma unroll
            for (int n = 0; n < 4; n++)
#pragma unroll
                for (int c = 0; c < 4; c++) s[n][c] *= scale;
        }

        // Online softmax over this group's 32 columns
        float mx0 = -1e30f, mx1 = -1e30f;
#pragma unroll
        for (int n = 0; n < 4; n++) {
            mx0 = fmaxf(mx0, fmaxf(s[n][0], s[n][1]));
            mx1 = fmaxf(mx1, fmaxf(s[n][2], s[n][3]));
        }
        mx0 = fmaxf(mx0, __shfl_xor_sync(0xffffffffu, mx0, 1));
        mx0 = fmaxf(mx0, __shfl_xor_sync(0xffffffffu, mx0, 2));
        mx1 = fmaxf(mx1, __shfl_xor_sync(0xffffffffu, mx1, 1));
        mx1 = fmaxf(mx1, __shfl_xor_sync(0xffffffffu, mx1, 2));

        float mn0 = fmaxf(m0, mx0);
        float mn1 = fmaxf(m1, mx1);
        float alpha0 = __expf(m0 - mn0);
        float alpha1 = __expf(m1 - mn1);
        m0 = mn0; m1 = mn1;

        float rs0 = 0.f, rs1 = 0.f;
#pragma unroll
        for (int n = 0; n < 4; n++) {
            s[n][0] = __expf(s[n][0] - mn0);
            s[n][1] = __expf(s[n][1] - mn0);
            s[n][2] = __expf(s[n][2] - mn1);
            s[n][3] = __expf(s[n][3] - mn1);
            rs0 += s[n][0] + s[n][1];
            rs1 += s[n][2] + s[n][3];
        }
        rs0 += __shfl_xor_sync(0xffffffffu, rs0, 1);
        rs0 += __shfl_xor_sync(0xffffffffu, rs0, 2);
        rs1 += __shfl_xor_sync(0xffffffffu, rs1, 1);
        rs1 += __shfl_xor_sync(0xffffffffu, rs1, 2);
        l0 = l0 * alpha0 + rs0;
        l1 = l1 * alpha1 + rs1;

#pragma unroll
        for (int n = 0; n < 8; n++) {
            o[n][0] *= alpha0; o[n][1] *= alpha0;
            o[n][2] *= alpha1; o[n][3] *= alpha1;
        }

        // Stage P (group-private; produced & consumed by the same warp rows)
#pragma unroll
        for (int n = 0; n < 4; n++) {
            int cb = 8 * n + 2 * l3;
            sPg[(r0) * 36 + cb + 0]     = f2tf32(s[n][0]);
            sPg[(r0) * 36 + cb + 1]     = f2tf32(s[n][1]);
            sPg[(r0 + 8) * 36 + cb + 0] = f2tf32(s[n][2]);
            sPg[(r0 + 8) * 36 + cb + 1] = f2tf32(s[n][3]);
        }
        __syncwarp();

        // O += P_half(16x32) . V_half(32x64)
#pragma unroll
        for (int ks = 0; ks < 4; ks++) {
            int k0 = 8 * ks;
            uint32_t a0 = sPg[(r0) * 36 + k0 + l3];
            uint32_t a1 = sPg[(r0 + 8) * 36 + k0 + l3];
            uint32_t a2 = sPg[(r0) * 36 + k0 + l3 + 4];
            uint32_t a3 = sPg[(r0 + 8) * 36 + k0 + l3 + 4];
#pragma unroll
            for (int n = 0; n < 8; n++) {
                int vr = 32 * g + k0 + l3;
                uint32_t b0 = sVc[(vr) * 72 + 8 * n + gid];
                uint32_t b1 = sVc[(vr + 4) * 72 + 8 * n + gid];
                mma_tf32(o[n], a0, a1, a2, a3, b0, b1);
            }
        }

        __syncthreads();      // stage st fully consumed by all warps

        if (kt + 2 <= qt) {
#pragma unroll
            for (int i = 0; i < 4; i++) {
                int id = t + i * 256;
                int r  = id >> 4;
                int c  = (id & 15) << 2;
                CPA16(su + (SK + st * 4352 + r * 68 + c) * 4,
                      &K[(size_t)((kt + 2) * 64 + r) * HEAD + c]);
                CPA16(su + (SV + st * 4608 + r * 72 + c) * 4,
                      &V[(size_t)((kt + 2) * 64 + r) * HEAD + c]);
            }
        }
        CPA_COMMIT();
    }

    CPA_WAIT0();
    __syncthreads();

    // ---- Merge the two groups' partial (m, l, O) ----
    float* sML = (float*)(smem + SP);        // [2][64][2]
    if (l3 == 0) {
        sML[((g * 64 + r0)     << 1) + 0] = m0;
        sML[((g * 64 + r0)     << 1) + 1] = l0;
        sML[((g * 64 + r0 + 8) << 1) + 0] = m1;
        sML[((g * 64 + r0 + 8) << 1) + 1] = l1;
    }
    __syncthreads();
    const int og = 1 - g;
    float mo0 = sML[((og * 64 + r0)     << 1) + 0];
    float lo0 = sML[((og * 64 + r0)     << 1) + 1];
    float mo1 = sML[((og * 64 + r0 + 8) << 1) + 0];
    float lo1 = sML[((og * 64 + r0 + 8) << 1) + 1];

    float M0 = fmaxf(m0, mo0), M1 = fmaxf(m1, mo1);
    float sc0 = __expf(m0 - M0), sc1 = __expf(m1 - M1);
    float L0 = l0 * sc0 + lo0 * __expf(mo0 - M0);
    float L1 = l1 * sc1 + lo1 * __expf(mo1 - M1);

#pragma unroll
    for (int n = 0; n < 8; n++) {
        o[n][0] *= sc0; o[n][1] *= sc0;
        o[n][2] *= sc1; o[n][3] *= sc1;
    }

    float* sOB = (float*)smem;               // reuse sQ region, 64 x 68
    if (g == 1) {
#pragma unroll
        for (int n = 0; n < 8; n++) {
            int cb = 8 * n + 2 * l3;
            sOB[(r0) * 68 + cb + 0]     = o[n][0];
            sOB[(r0) * 68 + cb + 1]     = o[n][1];
            sOB[(r0 + 8) * 68 + cb + 0] = o[n][2];
            sOB[(r0 + 8) * 68 + cb + 1] = o[n][3];
        }
    }
    __syncthreads();
    if (g == 0) {
        float inv0 = 1.f / L0;
        float inv1 = 1.f / L1;
        size_t orow0 = (size_t)b * SEQ + qt * 64 + r0;
#pragma unroll
        for (int n = 0; n < 8; n++) {
            int cb = 8 * n + 2 * l3;
            float2 v0, v1;
            v0.x = (o[n][0] + sOB[(r0) * 68 + cb + 0])     * inv0;
            v0.y = (o[n][1] + sOB[(r0) * 68 + cb + 1])     * inv0;
            v1.x = (o[n][2] + sOB[(r0 + 8) * 68 + cb + 0]) * inv1;
            v1.y = (o[n][3] + sOB[(r0 + 8) * 68 + cb + 1]) * inv1;
            *(float2*)&out[orow0 * HEAD + cb]       = v0;
            *(float2*)&out[(orow0 + 8) * HEAD + cb] = v1;
        }
    }
}

extern "C" void kernel_launch(void* const* d_in, const int* in_sizes, int n_in,
                              void* d_out, int out_size)
{
    const float* x  = (const float*)d_in[0];
    const float* Wq = (const float*)d_in[1];
    const float* bq = (const float*)d_in[2];
    const float* Wk = (const float*)d_in[3];
    const float* bk = (const float*)d_in[4];
    const float* Wv = (const float*)d_in[5];
    const float* bv = (const float*)d_in[6];
    float* out = (float*)d_out;

    const size_t QKV_SMEM = (size_t)(128 * 68 + 64 * 72) * sizeof(uint32_t);   // 53248
    cudaFuncSetAttribute(qkv_kernel, cudaFuncAttributeMaxDynamicSharedMemorySize,
                         (int)QKV_SMEM);
    qkv_kernel<<<dim3(SEQ * BATCH / 128, 3), 256, QKV_SMEM>>>(x, Wq, bq, Wk, bk, Wv, bv);

    // sQ 4352 + K 2*4352 + V 2*4608 + P 2*2304 = 26880 words = 107520 B
    const size_t FLASH_SMEM = (size_t)26880 * sizeof(uint32_t);
    cudaFuncSetAttribute(flash_kernel, cudaFuncAttributeMaxDynamicSharedMemorySize,
                         (int)FLASH_SMEM);
    flash_kernel<<<dim3(SEQ / 64, BATCH), 256, FLASH_SMEM>>>(out);
}